// round 2
// baseline (speedup 1.0000x reference)
#include <cuda_runtime.h>
#include <math.h>

// Problem shape (fixed by the dataset): [B=32, C=1, H=512, W=512] fp32.
#define BATCH 32
#define HH 512
#define WW 512
#define KER 31
#define PAD 15
#define NPIX (HH * WW)
#define HSEG 128  // vertical pass segment length

// Scratch: vertical box-sum of target. 32 MB static device array (allowed).
__device__ float g_s1[(size_t)BATCH * NPIX];
// Per-batch accumulators: [b][0]=sum(weit), [1]=sum(weit*bce), [2]=inter, [3]=union
__device__ double g_acc[BATCH][4];

// ---------------------------------------------------------------------------
// Kernel 0: zero the accumulators (graph-safe, deterministic re-init)
// ---------------------------------------------------------------------------
__global__ void zero_acc_kernel() {
    int i = threadIdx.x;
    if (i < BATCH * 4) ((double*)g_acc)[i] = 0.0;
}

// ---------------------------------------------------------------------------
// Kernel 1: vertical sliding box-sum of t (window 31, zero pad 15).
// Each thread owns one (b, w) column over a 128-row segment.
// grid = (WW/256, HH/HSEG, BATCH), block = 256. Coalesced across w.
// ---------------------------------------------------------------------------
__global__ void vsum_kernel(const float* __restrict__ t) {
    const int w   = blockIdx.x * blockDim.x + threadIdx.x;
    const int h0  = blockIdx.y * HSEG;
    const int b   = blockIdx.z;

    const float* tc = t + (size_t)b * NPIX + w;
    float*       sc = g_s1 + (size_t)b * NPIX + w;

    // initial window for row h0: rows [h0-15, h0+15] clipped to [0, H)
    float s = 0.0f;
    int lo = h0 - PAD; if (lo < 0) lo = 0;
    int hi = h0 + PAD; if (hi > HH - 1) hi = HH - 1;
    for (int r = lo; r <= hi; ++r) s += tc[(size_t)r * WW];
    sc[(size_t)h0 * WW] = s;

    for (int h = h0 + 1; h < h0 + HSEG; ++h) {
        const int add = h + PAD;
        const int sub = h - PAD - 1;
        if (add < HH) s += tc[(size_t)add * WW];
        if (sub >= 0) s -= tc[(size_t)sub * WW];
        sc[(size_t)h * WW] = s;
    }
}

// ---------------------------------------------------------------------------
// Kernel 2: horizontal 31-tap on the vertical sums + full fused elementwise
// math + per-batch reduction. One block per (b, h) row; 512 threads (one per w).
// ---------------------------------------------------------------------------
__inline__ __device__ float warp_reduce(float v) {
    #pragma unroll
    for (int o = 16; o > 0; o >>= 1) v += __shfl_down_sync(0xffffffffu, v, o);
    return v;
}

__global__ void fused_kernel(const float* __restrict__ x,
                             const float* __restrict__ t) {
    const int h = blockIdx.x;
    const int b = blockIdx.y;
    const int w = threadIdx.x;  // 0..511

    __shared__ float sh[WW + 2 * PAD];  // zero-padded row of vertical sums
    __shared__ float red[16][4];

    const size_t rowoff = ((size_t)b * HH + h) * (size_t)WW;

    sh[w + PAD] = g_s1[rowoff + w];
    if (w < PAD) {
        sh[w] = 0.0f;
        sh[WW + PAD + w] = 0.0f;
    }
    __syncthreads();

    // horizontal 31-tap box sum
    float hs = 0.0f;
    #pragma unroll
    for (int j = 0; j < KER; ++j) hs += sh[w + j];

    const float avg = hs * (1.0f / (float)(KER * KER));
    const float tt  = t[rowoff + w];
    const float xx  = x[rowoff + w];

    const float weit = 1.0f + 5.0f * fabsf(avg - tt);
    const float bce  = fmaxf(xx, 0.0f) - xx * tt + log1pf(expf(-fabsf(xx)));
    const float p    = 1.0f / (1.0f + expf(-xx));

    float a0 = weit;
    float a1 = weit * bce;
    float a2 = p * tt * weit;
    float a3 = (p + tt) * weit;

    a0 = warp_reduce(a0);
    a1 = warp_reduce(a1);
    a2 = warp_reduce(a2);
    a3 = warp_reduce(a3);

    const int warp = threadIdx.x >> 5;
    const int lane = threadIdx.x & 31;
    if (lane == 0) {
        red[warp][0] = a0; red[warp][1] = a1;
        red[warp][2] = a2; red[warp][3] = a3;
    }
    __syncthreads();

    if (warp == 0) {
        float r0 = (lane < 16) ? red[lane][0] : 0.0f;
        float r1 = (lane < 16) ? red[lane][1] : 0.0f;
        float r2 = (lane < 16) ? red[lane][2] : 0.0f;
        float r3 = (lane < 16) ? red[lane][3] : 0.0f;
        r0 = warp_reduce(r0);
        r1 = warp_reduce(r1);
        r2 = warp_reduce(r2);
        r3 = warp_reduce(r3);
        if (lane == 0) {
            atomicAdd(&g_acc[b][0], (double)r0);
            atomicAdd(&g_acc[b][1], (double)r1);
            atomicAdd(&g_acc[b][2], (double)r2);
            atomicAdd(&g_acc[b][3], (double)r3);
        }
    }
}

// ---------------------------------------------------------------------------
// Kernel 3: combine per-batch accumulators into the scalar mean loss.
// ---------------------------------------------------------------------------
__global__ void finalize_kernel(float* __restrict__ out) {
    const int b = threadIdx.x;  // 32 threads
    double loss = 0.0;
    if (b < BATCH) {
        const double wsum  = g_acc[b][0];
        const double num   = g_acc[b][1];
        const double inter = g_acc[b][2];
        const double uni   = g_acc[b][3];
        const double wbce = num / wsum;
        const double wiou = 1.0 - (inter + 1.0) / (uni - inter + 1.0);
        loss = wbce + wiou;
    }
    #pragma unroll
    for (int o = 16; o > 0; o >>= 1) loss += __shfl_down_sync(0xffffffffu, loss, o);
    if (b == 0) out[0] = (float)(loss / (double)BATCH);
}

// ---------------------------------------------------------------------------
extern "C" void kernel_launch(void* const* d_in, const int* in_sizes, int n_in,
                              void* d_out, int out_size) {
    const float* x = (const float*)d_in[0];  // input (logits)
    const float* t = (const float*)d_in[1];  // target
    float* out = (float*)d_out;

    zero_acc_kernel<<<1, 128>>>();
    {
        dim3 grid(WW / 256, HH / HSEG, BATCH);
        vsum_kernel<<<grid, 256>>>(t);
    }
    {
        dim3 grid(HH, BATCH);
        fused_kernel<<<grid, WW>>>(x, t);
    }
    finalize_kernel<<<1, 32>>>(out);
}

// round 3
// speedup vs baseline: 1.4333x; 1.4333x over previous
#include <cuda_runtime.h>
#include <math.h>

// Problem shape (fixed by the dataset): [B=32, C=1, H=512, W=512] fp32.
#define BATCH 32
#define HH 512
#define WW 512
#define KER 31
#define PAD 15
#define NPIX (HH * WW)
#define HSEG 128  // vertical pass segment length

// Scratch: vertical box-sum of target (32 MB static device array — allowed).
__device__ float g_s1[(size_t)BATCH * NPIX];
// Per-(batch,row) partials: x=sum(weit), y=sum(weit*bce), z=inter, w=union
__device__ float4 g_part[BATCH][HH];

// ---------------------------------------------------------------------------
// Kernel 1: vertical sliding box-sum of t (window 31, zero pad 15).
// Each thread owns one (b, w) column over a 128-row segment.
// grid = (WW/256, HH/HSEG, BATCH), block = 256. Coalesced across w.
// ---------------------------------------------------------------------------
__global__ void vsum_kernel(const float* __restrict__ t) {
    const int w   = blockIdx.x * blockDim.x + threadIdx.x;
    const int h0  = blockIdx.y * HSEG;
    const int b   = blockIdx.z;

    const float* tc = t + (size_t)b * NPIX + w;
    float*       sc = g_s1 + (size_t)b * NPIX + w;

    // initial window for row h0: rows [h0-15, h0+15] clipped to [0, H)
    float s = 0.0f;
    int lo = h0 - PAD; if (lo < 0) lo = 0;
    int hi = h0 + PAD; if (hi > HH - 1) hi = HH - 1;
    #pragma unroll 4
    for (int r = lo; r <= hi; ++r) s += tc[(size_t)r * WW];
    sc[(size_t)h0 * WW] = s;

    #pragma unroll 4
    for (int h = h0 + 1; h < h0 + HSEG; ++h) {
        const int add = h + PAD;
        const int sub = h - PAD - 1;
        if (add < HH) s += tc[(size_t)add * WW];
        if (sub >= 0) s -= tc[(size_t)sub * WW];
        sc[(size_t)h * WW] = s;
    }
}

// ---------------------------------------------------------------------------
// Kernel 2: horizontal 31-tap on the vertical sums + fused elementwise math
// + per-row reduction. One block per (b, h) row; 128 threads, 4 columns each.
// ---------------------------------------------------------------------------
__inline__ __device__ float warp_reduce(float v) {
    #pragma unroll
    for (int o = 16; o > 0; o >>= 1) v += __shfl_down_sync(0xffffffffu, v, o);
    return v;
}

__global__ void fused_kernel(const float* __restrict__ x,
                             const float* __restrict__ t) {
    const int h   = blockIdx.x;
    const int b   = blockIdx.y;
    const int tid = threadIdx.x;  // 0..127, owns columns 4*tid .. 4*tid+3

    __shared__ float sh[16 + WW + 16];  // zero-padded vsum row (col c at sh[16+c])
    __shared__ float red4[4][4];

    const size_t rowoff = ((size_t)b * HH + h) * (size_t)WW;

    // load vertical sums for this row (float4, coalesced) into padded shared
    float4 vs = ((const float4*)(g_s1 + rowoff))[tid];
    if (tid < 16) { sh[tid] = 0.0f; sh[16 + WW + tid] = 0.0f; }
    ((float4*)(sh + 16))[tid] = vs;
    __syncthreads();

    // Load window sh[4t .. 4t+35] as 9 aligned float4s.
    // Output col c uses indices c+1 .. c+31 (since col c lives at sh[16+c]).
    float v[36];
    {
        const float4* p = (const float4*)(sh + 4 * tid);
        #pragma unroll
        for (int i = 0; i < 9; ++i) {
            float4 q = p[i];
            v[4*i] = q.x; v[4*i+1] = q.y; v[4*i+2] = q.z; v[4*i+3] = q.w;
        }
    }

    // S0 = sum v[1..31]; slide for S1..S3
    float sA = 0.f, sB = 0.f, sC = 0.f, sD = 0.f;
    #pragma unroll
    for (int i = 1; i <= 28; i += 4) {
        sA += v[i]; sB += v[i+1]; sC += v[i+2]; sD += v[i+3];
    }
    sA += v[29]; sB += v[30]; sC += v[31];
    float S[4];
    S[0] = (sA + sB) + (sC + sD);
    S[1] = S[0] - v[1] + v[32];
    S[2] = S[1] - v[2] + v[33];
    S[3] = S[2] - v[3] + v[34];

    const float4 t4 = ((const float4*)(t + rowoff))[tid];
    const float4 x4 = ((const float4*)(x + rowoff))[tid];
    const float tt_[4] = {t4.x, t4.y, t4.z, t4.w};
    const float xx_[4] = {x4.x, x4.y, x4.z, x4.w};

    float a0 = 0.f, a1 = 0.f, a2 = 0.f, a3 = 0.f;
    const float inv = 1.0f / (float)(KER * KER);
    #pragma unroll
    for (int k = 0; k < 4; ++k) {
        const float tt = tt_[k];
        const float xx = xx_[k];
        const float weit = 1.0f + 5.0f * fabsf(S[k] * inv - tt);
        const float e    = __expf(-fabsf(xx));        // e^{-|x|} in (0,1]
        const float bce  = fmaxf(xx, 0.0f) - xx * tt + __logf(1.0f + e);
        const float p    = (xx >= 0.0f ? 1.0f : e) / (1.0f + e);  // sigmoid(x)
        a0 += weit;
        a1 += weit * bce;
        a2 += p * tt * weit;
        a3 += (p + tt) * weit;
    }

    a0 = warp_reduce(a0);
    a1 = warp_reduce(a1);
    a2 = warp_reduce(a2);
    a3 = warp_reduce(a3);

    const int warp = tid >> 5;
    const int lane = tid & 31;
    if (lane == 0) {
        red4[warp][0] = a0; red4[warp][1] = a1;
        red4[warp][2] = a2; red4[warp][3] = a3;
    }
    __syncthreads();

    if (tid < 4) {
        float r = red4[0][tid] + red4[1][tid] + red4[2][tid] + red4[3][tid];
        ((float*)&g_part[b][h])[tid] = r;
    }
}

// ---------------------------------------------------------------------------
// Kernel 3: reduce per-row partials -> per-batch loss -> scalar mean.
// One block, 1024 threads; warp w handles batch w.
// ---------------------------------------------------------------------------
__global__ void finalize_kernel(float* __restrict__ out) {
    const int warp = threadIdx.x >> 5;  // batch index, 0..31
    const int lane = threadIdx.x & 31;

    float a0 = 0.f, a1 = 0.f, a2 = 0.f, a3 = 0.f;
    for (int r = lane; r < HH; r += 32) {
        float4 q = g_part[warp][r];
        a0 += q.x; a1 += q.y; a2 += q.z; a3 += q.w;
    }
    a0 = warp_reduce(a0);
    a1 = warp_reduce(a1);
    a2 = warp_reduce(a2);
    a3 = warp_reduce(a3);

    __shared__ float losses[32];
    if (lane == 0) {
        const float wbce = a1 / a0;
        const float wiou = 1.0f - (a2 + 1.0f) / ((a3 - a2) + 1.0f);
        losses[warp] = wbce + wiou;
    }
    __syncthreads();

    if (warp == 0) {
        float l = losses[lane];
        l = warp_reduce(l);
        if (lane == 0) out[0] = l * (1.0f / (float)BATCH);
    }
}

// ---------------------------------------------------------------------------
extern "C" void kernel_launch(void* const* d_in, const int* in_sizes, int n_in,
                              void* d_out, int out_size) {
    const float* x = (const float*)d_in[0];  // input (logits)
    const float* t = (const float*)d_in[1];  // target
    float* out = (float*)d_out;

    {
        dim3 grid(WW / 256, HH / HSEG, BATCH);
        vsum_kernel<<<grid, 256>>>(t);
    }
    {
        dim3 grid(HH, BATCH);
        fused_kernel<<<grid, 128>>>(x, t);
    }
    finalize_kernel<<<1, 1024>>>(out);
}

// round 4
// speedup vs baseline: 2.7940x; 1.9494x over previous
#include <cuda_runtime.h>
#include <math.h>

// Problem shape (fixed by the dataset): [B=32, C=1, H=512, W=512] fp32.
#define BATCH 32
#define HH 512
#define WW 512
#define W4 (WW / 4)   // 128 float4 per row
#define KER 31
#define PAD 15
#define NPIX (HH * WW)
#define HSEG 32       // vertical pass segment length (short => parallel + low latency)

// Scratch: vertical box-sum of target (32 MB static device array — allowed).
__device__ float g_s1[(size_t)BATCH * NPIX];
// Per-(batch,row) partials: x=sum(weit), y=sum(weit*bce), z=inter, w=union
__device__ float4 g_part[BATCH][HH];

// ---------------------------------------------------------------------------
// Kernel 1: vertical sliding box-sum of t (window 31, zero pad 15).
// Each thread owns 4 adjacent columns (one float4) over a 32-row segment.
// grid = (1, HH/HSEG, BATCH), block = 128 (covers all 512 cols as float4).
// 512 blocks x 128 thr; ~1.94x L2-read amplification traded for 8x parallelism.
// ---------------------------------------------------------------------------
__global__ void vsum_kernel(const float* __restrict__ t) {
    const int c4 = threadIdx.x;            // float4 column group 0..127
    const int h0 = blockIdx.y * HSEG;
    const int b  = blockIdx.z;

    const float4* tc = (const float4*)(t + (size_t)b * NPIX) + c4;
    float4*       sc = (float4*)(g_s1 + (size_t)b * NPIX) + c4;

    // initial window for row h0: rows [h0-15, h0+15] clipped to [0, H)
    float4 s = make_float4(0.f, 0.f, 0.f, 0.f);
    const int lo = (h0 - PAD < 0) ? 0 : h0 - PAD;
    const int hi = (h0 + PAD > HH - 1) ? HH - 1 : h0 + PAD;
    #pragma unroll 8
    for (int r = lo; r <= hi; ++r) {
        float4 q = tc[(size_t)r * W4];
        s.x += q.x; s.y += q.y; s.z += q.z; s.w += q.w;
    }
    sc[(size_t)h0 * W4] = s;

    #pragma unroll 8
    for (int h = h0 + 1; h < h0 + HSEG; ++h) {
        const int add = h + PAD;
        const int sub = h - PAD - 1;
        if (add < HH) {
            float4 q = tc[(size_t)add * W4];
            s.x += q.x; s.y += q.y; s.z += q.z; s.w += q.w;
        }
        if (sub >= 0) {
            float4 q = tc[(size_t)sub * W4];
            s.x -= q.x; s.y -= q.y; s.z -= q.z; s.w -= q.w;
        }
        sc[(size_t)h * W4] = s;
    }
}

// ---------------------------------------------------------------------------
// Kernel 2: horizontal 31-tap on the vertical sums + fused elementwise math
// + per-row reduction. One block per (b, h) row; 128 threads, 4 columns each.
// ---------------------------------------------------------------------------
__inline__ __device__ float warp_reduce(float v) {
    #pragma unroll
    for (int o = 16; o > 0; o >>= 1) v += __shfl_down_sync(0xffffffffu, v, o);
    return v;
}

__global__ void fused_kernel(const float* __restrict__ x,
                             const float* __restrict__ t) {
    const int h   = blockIdx.x;
    const int b   = blockIdx.y;
    const int tid = threadIdx.x;  // 0..127, owns columns 4*tid .. 4*tid+3

    __shared__ float sh[16 + WW + 16];  // zero-padded vsum row (col c at sh[16+c])
    __shared__ float red4[4][4];

    const size_t rowoff = ((size_t)b * HH + h) * (size_t)WW;

    // load vertical sums for this row (float4, coalesced) into padded shared
    float4 vs = ((const float4*)(g_s1 + rowoff))[tid];
    if (tid < 16) { sh[tid] = 0.0f; sh[16 + WW + tid] = 0.0f; }
    ((float4*)(sh + 16))[tid] = vs;
    __syncthreads();

    // Load window sh[4t .. 4t+35] as 9 aligned float4s.
    // Output col c uses indices c+1 .. c+31 (since col c lives at sh[16+c]).
    float v[36];
    {
        const float4* p = (const float4*)(sh + 4 * tid);
        #pragma unroll
        for (int i = 0; i < 9; ++i) {
            float4 q = p[i];
            v[4*i] = q.x; v[4*i+1] = q.y; v[4*i+2] = q.z; v[4*i+3] = q.w;
        }
    }

    // S0 = sum v[1..31]; slide for S1..S3
    float sA = 0.f, sB = 0.f, sC = 0.f, sD = 0.f;
    #pragma unroll
    for (int i = 1; i <= 28; i += 4) {
        sA += v[i]; sB += v[i+1]; sC += v[i+2]; sD += v[i+3];
    }
    sA += v[29]; sB += v[30]; sC += v[31];
    float S[4];
    S[0] = (sA + sB) + (sC + sD);
    S[1] = S[0] - v[1] + v[32];
    S[2] = S[1] - v[2] + v[33];
    S[3] = S[2] - v[3] + v[34];

    const float4 t4 = ((const float4*)(t + rowoff))[tid];
    const float4 x4 = ((const float4*)(x + rowoff))[tid];
    const float tt_[4] = {t4.x, t4.y, t4.z, t4.w};
    const float xx_[4] = {x4.x, x4.y, x4.z, x4.w};

    float a0 = 0.f, a1 = 0.f, a2 = 0.f, a3 = 0.f;
    const float inv = 1.0f / (float)(KER * KER);
    #pragma unroll
    for (int k = 0; k < 4; ++k) {
        const float tt = tt_[k];
        const float xx = xx_[k];
        const float weit = 1.0f + 5.0f * fabsf(S[k] * inv - tt);
        const float e    = __expf(-fabsf(xx));        // e^{-|x|} in (0,1]
        const float bce  = fmaxf(xx, 0.0f) - xx * tt + __logf(1.0f + e);
        const float p    = (xx >= 0.0f ? 1.0f : e) / (1.0f + e);  // sigmoid(x)
        a0 += weit;
        a1 += weit * bce;
        a2 += p * tt * weit;
        a3 += (p + tt) * weit;
    }

    a0 = warp_reduce(a0);
    a1 = warp_reduce(a1);
    a2 = warp_reduce(a2);
    a3 = warp_reduce(a3);

    const int warp = tid >> 5;
    const int lane = tid & 31;
    if (lane == 0) {
        red4[warp][0] = a0; red4[warp][1] = a1;
        red4[warp][2] = a2; red4[warp][3] = a3;
    }
    __syncthreads();

    if (tid < 4) {
        float r = red4[0][tid] + red4[1][tid] + red4[2][tid] + red4[3][tid];
        ((float*)&g_part[b][h])[tid] = r;
    }
}

// ---------------------------------------------------------------------------
// Kernel 3: reduce per-row partials -> per-batch loss -> scalar mean.
// One block, 1024 threads; warp w handles batch w.
// ---------------------------------------------------------------------------
__global__ void finalize_kernel(float* __restrict__ out) {
    const int warp = threadIdx.x >> 5;  // batch index, 0..31
    const int lane = threadIdx.x & 31;

    float a0 = 0.f, a1 = 0.f, a2 = 0.f, a3 = 0.f;
    for (int r = lane; r < HH; r += 32) {
        float4 q = g_part[warp][r];
        a0 += q.x; a1 += q.y; a2 += q.z; a3 += q.w;
    }
    a0 = warp_reduce(a0);
    a1 = warp_reduce(a1);
    a2 = warp_reduce(a2);
    a3 = warp_reduce(a3);

    __shared__ float losses[32];
    if (lane == 0) {
        const float wbce = a1 / a0;
        const float wiou = 1.0f - (a2 + 1.0f) / ((a3 - a2) + 1.0f);
        losses[warp] = wbce + wiou;
    }
    __syncthreads();

    if (warp == 0) {
        float l = losses[lane];
        l = warp_reduce(l);
        if (lane == 0) out[0] = l * (1.0f / (float)BATCH);
    }
}

// ---------------------------------------------------------------------------
extern "C" void kernel_launch(void* const* d_in, const int* in_sizes, int n_in,
                              void* d_out, int out_size) {
    const float* x = (const float*)d_in[0];  // input (logits)
    const float* t = (const float*)d_in[1];  // target
    float* out = (float*)d_out;

    {
        dim3 grid(1, HH / HSEG, BATCH);
        vsum_kernel<<<grid, 128>>>(t);
    }
    {
        dim3 grid(HH, BATCH);
        fused_kernel<<<grid, 128>>>(x, t);
    }
    finalize_kernel<<<1, 1024>>>(out);
}

// round 7
// speedup vs baseline: 3.7582x; 1.3451x over previous
#include <cuda_runtime.h>
#include <math.h>

// Problem shape (fixed by the dataset): [B=32, C=1, H=512, W=512] fp32.
#define BATCH 32
#define HH 512
#define WW 512
#define W4 (WW / 4)       // 128 float4 per row
#define KER 31
#define PAD 15
#define NPIX (HH * WW)
#define ROWS 16           // output rows per block
#define TILES (HH / ROWS) // 32
#define NBLOCKS (TILES * BATCH)  // 1024
#define STRIDE 544        // padded shared row: 16 + 512 + 16 floats

// Per-(batch,tile) partials: x=sum(weit), y=sum(weit*bce), z=inter, w=union
__device__ float4 g_part[BATCH][TILES];
__device__ int g_count = 0;   // last-block detector; self-resets each launch

__inline__ __device__ float warp_reduce(float v) {
    #pragma unroll
    for (int o = 16; o > 0; o >>= 1) v += __shfl_down_sync(0xffffffffu, v, o);
    return v;
}

__global__ void __launch_bounds__(128, 6)
structure_loss_kernel(const float* __restrict__ x,
                      const float* __restrict__ t,
                      float* __restrict__ out) {
    __shared__ float sh[ROWS * STRIDE];   // 16 vsum rows, zero-padded
    __shared__ float red4[4][4];
    __shared__ float sl[BATCH];
    __shared__ int s_last;

    const int tid  = threadIdx.x;   // 0..127, owns cols 4*tid..4*tid+3
    const int tile = blockIdx.x;    // 0..31
    const int b    = blockIdx.y;    // 0..31
    const int h0   = tile * ROWS;

    const float4* tc = (const float4*)(t + (size_t)b * NPIX) + tid;

    // zero the left/right pads of all 16 rows
    if (tid < 16) {
        #pragma unroll
        for (int j = 0; j < ROWS; ++j) {
            sh[j * STRIDE + tid]              = 0.0f;
            sh[j * STRIDE + 16 + WW + tid]    = 0.0f;
        }
    }

    // ---- vertical sliding 31-row box sum, written to shared ----
    float4 s = make_float4(0.f, 0.f, 0.f, 0.f);
    {
        const int lo = (h0 - PAD < 0) ? 0 : h0 - PAD;
        const int hi = (h0 + PAD > HH - 1) ? HH - 1 : h0 + PAD;
        #pragma unroll 4
        for (int r = lo; r <= hi; ++r) {
            float4 q = tc[(size_t)r * W4];
            s.x += q.x; s.y += q.y; s.z += q.z; s.w += q.w;
        }
    }
    ((float4*)(sh + 16))[tid] = s;

    #pragma unroll
    for (int j = 1; j < ROWS; ++j) {
        const int add = h0 + j + PAD;
        const int sub = h0 + j - PAD - 1;
        if (add < HH) {
            float4 q = tc[(size_t)add * W4];
            s.x += q.x; s.y += q.y; s.z += q.z; s.w += q.w;
        }
        if (sub >= 0) {
            float4 q = tc[(size_t)sub * W4];
            s.x -= q.x; s.y -= q.y; s.z -= q.z; s.w -= q.w;
        }
        ((float4*)(sh + j * STRIDE + 16))[tid] = s;
    }
    __syncthreads();

    // ---- horizontal 31-tap + elementwise math + accumulation over 16 rows ----
    float a0 = 0.f, a1 = 0.f, a2 = 0.f, a3 = 0.f;
    const float inv = 1.0f / (float)(KER * KER);

    #pragma unroll 2
    for (int j = 0; j < ROWS; ++j) {
        // window sh_row[4t .. 4t+35] as 9 aligned float4s; col c at offset 16+c
        float v[36];
        {
            const float4* p = (const float4*)(sh + j * STRIDE + 4 * tid);
            #pragma unroll
            for (int i = 0; i < 9; ++i) {
                float4 q = p[i];
                v[4*i] = q.x; v[4*i+1] = q.y; v[4*i+2] = q.z; v[4*i+3] = q.w;
            }
        }
        float sA = 0.f, sB = 0.f, sC = 0.f, sD = 0.f;
        #pragma unroll
        for (int i = 1; i <= 28; i += 4) {
            sA += v[i]; sB += v[i+1]; sC += v[i+2]; sD += v[i+3];
        }
        sA += v[29]; sB += v[30]; sC += v[31];
        float S[4];
        S[0] = (sA + sB) + (sC + sD);
        S[1] = S[0] - v[1] + v[32];
        S[2] = S[1] - v[2] + v[33];
        S[3] = S[2] - v[3] + v[34];

        const size_t rowoff = ((size_t)b * HH + h0 + j) * (size_t)WW + 4 * tid;
        const float4 t4 = *(const float4*)(t + rowoff);
        const float4 x4 = *(const float4*)(x + rowoff);
        const float tt_[4] = {t4.x, t4.y, t4.z, t4.w};
        const float xx_[4] = {x4.x, x4.y, x4.z, x4.w};

        #pragma unroll
        for (int k = 0; k < 4; ++k) {
            const float tt = tt_[k];
            const float xx = xx_[k];
            const float weit = 1.0f + 5.0f * fabsf(S[k] * inv - tt);
            const float e    = __expf(-fabsf(xx));                    // e^{-|x|}
            const float bce  = fmaxf(xx, 0.0f) - xx * tt + __logf(1.0f + e);
            const float p    = (xx >= 0.0f ? 1.0f : e) / (1.0f + e);  // sigmoid
            a0 += weit;
            a1 += weit * bce;
            a2 += p * tt * weit;
            a3 += (p + tt) * weit;
        }
    }

    // ---- block reduce -> one float4 per block ----
    a0 = warp_reduce(a0);
    a1 = warp_reduce(a1);
    a2 = warp_reduce(a2);
    a3 = warp_reduce(a3);
    const int warp = tid >> 5;
    const int lane = tid & 31;
    if (lane == 0) {
        red4[warp][0] = a0; red4[warp][1] = a1;
        red4[warp][2] = a2; red4[warp][3] = a3;
    }
    __syncthreads();

    if (tid == 0) {
        float4 r;
        r.x = (red4[0][0] + red4[1][0]) + (red4[2][0] + red4[3][0]);
        r.y = (red4[0][1] + red4[1][1]) + (red4[2][1] + red4[3][1]);
        r.z = (red4[0][2] + red4[1][2]) + (red4[2][2] + red4[3][2]);
        r.w = (red4[0][3] + red4[1][3]) + (red4[2][3] + red4[3][3]);
        g_part[b][tile] = r;
        __threadfence();
        int prev = atomicAdd(&g_count, 1);
        s_last = (prev == NBLOCKS - 1) ? 1 : 0;
        if (s_last) atomicExch(&g_count, 0);   // reset for next graph replay
    }
    __syncthreads();
    if (!s_last) return;

    // ---- last block: final reduction (fixed order => deterministic) ----
    __threadfence();  // acquire: see all g_part writes
    {
        // thread i: batch bb = i>>2, quarter p = i&3 -> tiles p*8 .. p*8+7
        const int bb = tid >> 2;
        const int p  = tid & 3;
        float c0 = 0.f, c1 = 0.f, c2 = 0.f, c3 = 0.f;
        #pragma unroll
        for (int k = 0; k < 8; ++k) {
            float4 q = g_part[bb][p * 8 + k];
            c0 += q.x; c1 += q.y; c2 += q.z; c3 += q.w;
        }
        #pragma unroll
        for (int o = 1; o <= 2; o <<= 1) {
            c0 += __shfl_xor_sync(0xffffffffu, c0, o);
            c1 += __shfl_xor_sync(0xffffffffu, c1, o);
            c2 += __shfl_xor_sync(0xffffffffu, c2, o);
            c3 += __shfl_xor_sync(0xffffffffu, c3, o);
        }
        if (p == 0) {
            const float wbce = c1 / c0;
            const float wiou = 1.0f - (c2 + 1.0f) / ((c3 - c2) + 1.0f);
            sl[bb] = wbce + wiou;
        }
    }
    __syncthreads();
    if (tid < 32) {
        float l = sl[tid];
        l = warp_reduce(l);
        if (tid == 0) out[0] = l * (1.0f / (float)BATCH);
    }
}

// ---------------------------------------------------------------------------
extern "C" void kernel_launch(void* const* d_in, const int* in_sizes, int n_in,
                              void* d_out, int out_size) {
    const float* x = (const float*)d_in[0];  // input (logits)
    const float* t = (const float*)d_in[1];  // target
    float* out = (float*)d_out;

    dim3 grid(TILES, BATCH);
    structure_loss_kernel<<<grid, 128>>>(x, t, out);
}

// round 8
// speedup vs baseline: 6.5194x; 1.7347x over previous
#include <cuda_runtime.h>
#include <math.h>

// Problem shape (fixed by the dataset): [B=32, C=1, H=512, W=512] fp32.
#define BATCH 32
#define HH 512
#define WW 512
#define W4 (WW / 4)       // 128 float4 per row
#define KER 31
#define PAD 15
#define NPIX (HH * WW)
#define ROWS 16           // output rows per block
#define TILES (HH / ROWS) // 32
#define NBLOCKS (TILES * BATCH)  // 1024

// Per-(batch,tile) partials: x=sum(weit), y=sum(weit*bce), z=inter, w=union
__device__ float4 g_part[BATCH][TILES];
__device__ int g_count = 0;   // last-block detector; self-resets each launch

__inline__ __device__ float warp_reduce(float v) {
    #pragma unroll
    for (int o = 16; o > 0; o >>= 1) v += __shfl_down_sync(0xffffffffu, v, o);
    return v;
}

// Padded per-row buffers: float4 index 4+tid holds thread tid's vsum (cols
// 4t..4t+3); indices 0..3 and 132..135 are zero pads (cols <0 and >=512).
// G[i] = sum of the 4 floats of P[i].
__global__ void __launch_bounds__(128, 8)
structure_loss_kernel(const float* __restrict__ x,
                      const float* __restrict__ t,
                      float* __restrict__ out) {
    __shared__ float4 Pb[2][136];
    __shared__ float  Gb[2][136];
    __shared__ float red4[4][4];
    __shared__ float sl[BATCH];
    __shared__ int s_last;

    const int tid  = threadIdx.x;   // 0..127, owns cols 4*tid..4*tid+3
    const int tile = blockIdx.x;    // 0..31
    const int b    = blockIdx.y;    // 0..31
    const int h0   = tile * ROWS;

    // zero the pads of both buffers (read-only thereafter)
    if (tid < 4) {
        const float4 z4 = make_float4(0.f, 0.f, 0.f, 0.f);
        Pb[0][tid] = z4;       Pb[1][tid] = z4;
        Pb[0][132 + tid] = z4; Pb[1][132 + tid] = z4;
        Gb[0][tid] = 0.f;       Gb[1][tid] = 0.f;
        Gb[0][132 + tid] = 0.f; Gb[1][132 + tid] = 0.f;
    }

    const float4* tc = (const float4*)(t + (size_t)b * NPIX) + tid;

    // ---- initial vertical window for row h0: rows [h0-15, h0+15] clipped ----
    float4 s = make_float4(0.f, 0.f, 0.f, 0.f);
    {
        const int lo = (h0 - PAD < 0) ? 0 : h0 - PAD;
        const int hi = (h0 + PAD > HH - 1) ? HH - 1 : h0 + PAD;
        #pragma unroll 4
        for (int r = lo; r <= hi; ++r) {
            float4 q = tc[(size_t)r * W4];
            s.x += q.x; s.y += q.y; s.z += q.z; s.w += q.w;
        }
    }

    float a0 = 0.f, a1 = 0.f, a2 = 0.f, a3 = 0.f;
    const float inv = 1.0f / (float)(KER * KER);

    #pragma unroll 2
    for (int j = 0; j < ROWS; ++j) {
        if (j > 0) {  // slide the vertical window down one row
            const int add = h0 + j + PAD;
            const int sub = h0 + j - PAD - 1;
            if (add < HH) {
                float4 q = tc[(size_t)add * W4];
                s.x += q.x; s.y += q.y; s.z += q.z; s.w += q.w;
            }
            if (sub >= 0) {
                float4 q = tc[(size_t)sub * W4];
                s.x -= q.x; s.y -= q.y; s.z -= q.z; s.w -= q.w;
            }
        }

        float4* P = Pb[j & 1];
        float*  G = Gb[j & 1];
        P[4 + tid] = s;
        G[4 + tid] = (s.x + s.y) + (s.z + s.w);
        __syncthreads();

        // horizontal 31-tap via group sums + neighbor edges
        const float4 sm = P[tid];      // cols 4t-16 .. 4t-13
        const float4 sp = P[tid + 8];  // cols 4t+16 .. 4t+19
        float S0 = G[tid] - sm.x;      // (G[t] - P[4t])
        #pragma unroll
        for (int i = 1; i < 8; ++i) S0 += G[tid + i];
        const float S1 = S0 - sm.y + sp.x;
        const float S2 = S1 - sm.z + sp.y;
        const float S3 = S2 - sm.w + sp.z;
        const float S[4] = {S0, S1, S2, S3};

        const size_t rowoff = ((size_t)b * HH + h0 + j) * (size_t)WW + 4 * tid;
        const float4 t4 = *(const float4*)(t + rowoff);
        const float4 x4 = *(const float4*)(x + rowoff);
        const float tt_[4] = {t4.x, t4.y, t4.z, t4.w};
        const float xx_[4] = {x4.x, x4.y, x4.z, x4.w};

        #pragma unroll
        for (int k = 0; k < 4; ++k) {
            const float tt = tt_[k];
            const float xx = xx_[k];
            const float weit = 1.0f + 5.0f * fabsf(S[k] * inv - tt);
            const float e    = __expf(-fabsf(xx));                    // e^{-|x|}
            const float bce  = fmaxf(xx, 0.0f) - xx * tt + __logf(1.0f + e);
            const float p    = __fdividef((xx >= 0.0f ? 1.0f : e), 1.0f + e);
            a0 += weit;
            a1 += weit * bce;
            a2 += p * tt * weit;
            a3 += (p + tt) * weit;
        }
    }

    // ---- block reduce -> one float4 per block ----
    a0 = warp_reduce(a0);
    a1 = warp_reduce(a1);
    a2 = warp_reduce(a2);
    a3 = warp_reduce(a3);
    const int warp = tid >> 5;
    const int lane = tid & 31;
    if (lane == 0) {
        red4[warp][0] = a0; red4[warp][1] = a1;
        red4[warp][2] = a2; red4[warp][3] = a3;
    }
    __syncthreads();

    if (tid == 0) {
        float4 r;
        r.x = (red4[0][0] + red4[1][0]) + (red4[2][0] + red4[3][0]);
        r.y = (red4[0][1] + red4[1][1]) + (red4[2][1] + red4[3][1]);
        r.z = (red4[0][2] + red4[1][2]) + (red4[2][2] + red4[3][2]);
        r.w = (red4[0][3] + red4[1][3]) + (red4[2][3] + red4[3][3]);
        g_part[b][tile] = r;
        __threadfence();
        int prev = atomicAdd(&g_count, 1);
        s_last = (prev == NBLOCKS - 1) ? 1 : 0;
        if (s_last) atomicExch(&g_count, 0);   // reset for next graph replay
    }
    __syncthreads();
    if (!s_last) return;

    // ---- last block: final reduction (fixed order => deterministic) ----
    __threadfence();  // acquire: see all g_part writes
    {
        // thread i: batch bb = i>>2, quarter p = i&3 -> tiles p*8 .. p*8+7
        const int bb = tid >> 2;
        const int p  = tid & 3;
        float c0 = 0.f, c1 = 0.f, c2 = 0.f, c3 = 0.f;
        #pragma unroll
        for (int k = 0; k < 8; ++k) {
            float4 q = g_part[bb][p * 8 + k];
            c0 += q.x; c1 += q.y; c2 += q.z; c3 += q.w;
        }
        #pragma unroll
        for (int o = 1; o <= 2; o <<= 1) {
            c0 += __shfl_xor_sync(0xffffffffu, c0, o);
            c1 += __shfl_xor_sync(0xffffffffu, c1, o);
            c2 += __shfl_xor_sync(0xffffffffu, c2, o);
            c3 += __shfl_xor_sync(0xffffffffu, c3, o);
        }
        if (p == 0) {
            const float wbce = c1 / c0;
            const float wiou = 1.0f - (c2 + 1.0f) / ((c3 - c2) + 1.0f);
            sl[bb] = wbce + wiou;
        }
    }
    __syncthreads();
    if (tid < 32) {
        float l = sl[tid];
        l = warp_reduce(l);
        if (tid == 0) out[0] = l * (1.0f / (float)BATCH);
    }
}

// ---------------------------------------------------------------------------
extern "C" void kernel_launch(void* const* d_in, const int* in_sizes, int n_in,
                              void* d_out, int out_size) {
    const float* x = (const float*)d_in[0];  // input (logits)
    const float* t = (const float*)d_in[1];  // target
    float* out = (float*)d_out;

    dim3 grid(TILES, BATCH);
    structure_loss_kernel<<<grid, 128>>>(x, t, out);
}